// round 8
// baseline (speedup 1.0000x reference)
#include <cuda_runtime.h>
#include <cuda_bf16.h>
#include <cstdint>

#define F 26
#define D 128
#define NROWS 100000
#define B 4096
#define T (B * 20)

// Warp per (feature, bag). Lane l owns the l-th float4 (16B) of each 512B row.
// Row gathers: global->shared cp.async, ring of 3 stages x 4 rows per warp
// (12 slots = 6KB/warp). wait_group 2 keeps up to 3 stages in flight.
// Stage indices come from smem via one LDS.128 (4 indices) instead of 4 SHFLs.
__global__ __launch_bounds__(128, 8) void ebag_pool_kernel(
    const float* __restrict__ tables,   // [F, NROWS, D]
    const int* __restrict__ values,     // [F, T]
    const int* __restrict__ offsets,    // [F, B+1]
    float* __restrict__ out)            // [B, F, D]
{
    __shared__ float4 buf[4][12][32];   // [warp][slot][lane] = 24KB
    __shared__ int4   idx_s[4][8];      // [warp][32 idx as 8 int4] = 512B

    const int lane = threadIdx.x & 31;
    const int warp = threadIdx.x >> 5;
    const int bag  = blockIdx.x * 4 + warp;
    const int f    = blockIdx.y;

    const int* offs = offsets + f * (B + 1);
    const int s = __ldg(offs + bag);
    const int e = __ldg(offs + bag + 1);

    const int* vals = values + (size_t)f * T;
    const char* tabb = reinterpret_cast<const char*>(
        tables + (size_t)f * NROWS * D);

    // shared-space byte address of buf[warp][0][lane]; slot k is +k*512B
    uint32_t sb0 = (uint32_t)__cvta_generic_to_shared(&buf[warp][0][lane]);
    int* idxw = reinterpret_cast<int*>(idx_s[warp]);
    const int4* idxv = idx_s[warp];

    float4 a0 = make_float4(0.f, 0.f, 0.f, 0.f);
    float4 a1 = make_float4(0.f, 0.f, 0.f, 0.f);

    for (int base = s; base < e; base += 32) {
        const int n = min(32, e - base);
        // One coalesced index load covers up to 32 bag entries; stage via smem.
        if (base + lane < e) idxw[lane] = __ldg(vals + base + lane);
        __syncwarp();

        const int nstage = (n + 3) >> 2;

        for (int st = 0; st < nstage; ++st) {
            const int cnt = min(4, n - st * 4);
            const int slot = (st % 3) * 4;
            int4 r4 = idxv[st];                 // 4 row indices, one LDS.128
            #pragma unroll
            for (int q = 0; q < 4; ++q) {
                if (q < cnt) {
                    int r = (q == 0) ? r4.x : (q == 1) ? r4.y : (q == 2) ? r4.z : r4.w;
                    const char* src = tabb + ((size_t)(unsigned)r << 9) + (lane << 4);
                    uint32_t dst = sb0 + (uint32_t)((slot + q) << 9);
                    asm volatile("cp.async.cg.shared.global [%0], [%1], 16;\n"
                                 :: "r"(dst), "l"(src));
                }
            }
            asm volatile("cp.async.commit_group;\n");

            // Consume stage st-2 while st-1 and st are still in flight.
            if (st >= 2) {
                asm volatile("cp.async.wait_group 2;\n");
                const int pslot = ((st - 2) % 3) * 4;
                #pragma unroll
                for (int q = 0; q < 4; ++q) {   // st-2 is always a full stage of 4
                    float4 v = buf[warp][pslot + q][lane];
                    if (q & 1) { a1.x += v.x; a1.y += v.y; a1.z += v.z; a1.w += v.w; }
                    else       { a0.x += v.x; a0.y += v.y; a0.z += v.z; a0.w += v.w; }
                }
            }
        }

        // Drain the last two stages.
        if (nstage >= 2) {
            asm volatile("cp.async.wait_group 1;\n");
            const int st = nstage - 2;
            const int pslot = (st % 3) * 4;
            #pragma unroll
            for (int q = 0; q < 4; ++q) {       // second-to-last stage is full
                float4 v = buf[warp][pslot + q][lane];
                if (q & 1) { a1.x += v.x; a1.y += v.y; a1.z += v.z; a1.w += v.w; }
                else       { a0.x += v.x; a0.y += v.y; a0.z += v.z; a0.w += v.w; }
            }
        }
        if (nstage >= 1) {
            asm volatile("cp.async.wait_group 0;\n");
            const int st = nstage - 1;
            const int pslot = (st % 3) * 4;
            const int cnt = n - st * 4;
            #pragma unroll
            for (int q = 0; q < 4; ++q) {
                if (q < cnt) {
                    float4 v = buf[warp][pslot + q][lane];
                    if (q & 1) { a1.x += v.x; a1.y += v.y; a1.z += v.z; a1.w += v.w; }
                    else       { a0.x += v.x; a0.y += v.y; a0.z += v.z; a0.w += v.w; }
                }
            }
        }
        __syncwarp();   // idx_s reuse safety for next chunk
    }

    float4 acc;
    acc.x = a0.x + a1.x;
    acc.y = a0.y + a1.y;
    acc.z = a0.z + a1.z;
    acc.w = a0.w + a1.w;

    // out[b][f][:] — always write (empty bags must be 0; d_out is poisoned)
    float4* o = reinterpret_cast<float4*>(out) + ((size_t)bag * F + f) * 32;
    o[lane] = acc;
}

extern "C" void kernel_launch(void* const* d_in, const int* in_sizes, int n_in,
                              void* d_out, int out_size) {
    const float* tables  = (const float*)d_in[0];
    const int*   values  = (const int*)d_in[1];
    const int*   offsets = (const int*)d_in[2];
    float* out = (float*)d_out;

    dim3 grid(B / 4, F);   // feature on y: blocks of one feature grouped -> L2 reuse
    dim3 block(128);       // 4 warps = 4 bags per block
    ebag_pool_kernel<<<grid, block>>>(tables, values, offsets, out);
}

// round 9
// speedup vs baseline: 1.0432x; 1.0432x over previous
#include <cuda_runtime.h>
#include <cuda_bf16.h>
#include <cstdint>

#define F 26
#define D 128
#define NROWS 100000
#define B 4096
#define T (B * 20)

// Warp per (feature, bag). Lane l owns the l-th float4 (16B) of each 512B row.
// Row gathers go global->shared via cp.async: in-flight data lives in smem,
// stages of 4 rows, double-buffered (8-row ring per warp = 4KB smem).
// 2 warps per block: minimizes resource holding on ragged bag lengths
// (block frees as soon as the longer of TWO bags finishes, not four).
__global__ __launch_bounds__(64, 24) void ebag_pool_kernel(
    const float* __restrict__ tables,   // [F, NROWS, D]
    const int* __restrict__ values,     // [F, T]
    const int* __restrict__ offsets,    // [F, B+1]
    float* __restrict__ out)            // [B, F, D]
{
    __shared__ float4 buf[2][8][32];    // [warp][row-slot][lane] = 8KB

    const int lane = threadIdx.x & 31;
    const int warp = threadIdx.x >> 5;
    const int bag  = blockIdx.x * 2 + warp;
    const int f    = blockIdx.y;

    const int* offs = offsets + f * (B + 1);
    const int s = __ldg(offs + bag);
    const int e = __ldg(offs + bag + 1);

    const int* vals = values + (size_t)f * T;
    const char* tabb = reinterpret_cast<const char*>(
        tables + (size_t)f * NROWS * D);

    // shared-space byte address of buf[warp][0][lane]; slot k is +k*512B
    uint32_t sb0 = (uint32_t)__cvta_generic_to_shared(&buf[warp][0][lane]);

    float4 a0 = make_float4(0.f, 0.f, 0.f, 0.f);
    float4 a1 = make_float4(0.f, 0.f, 0.f, 0.f);

    for (int base = s; base < e; base += 32) {
        const int n = min(32, e - base);
        // One coalesced index load covers up to 32 bag entries.
        int myidx = 0;
        if (base + lane < e) myidx = __ldg(vals + base + lane);

        const int nstage = (n + 3) >> 2;
        int sbuf = 0;
        int prevcnt = 0;

        for (int st = 0; st < nstage; ++st) {
            const int cnt = min(4, n - st * 4);
            #pragma unroll
            for (int q = 0; q < 4; ++q) {
                if (q < cnt) {
                    int r = __shfl_sync(0xffffffffu, myidx, st * 4 + q);
                    const char* src = tabb + ((size_t)(unsigned)r << 9) + (lane << 4);
                    uint32_t dst = sb0 + (uint32_t)((sbuf * 4 + q) << 9);
                    asm volatile("cp.async.cg.shared.global [%0], [%1], 16;\n"
                                 :: "r"(dst), "l"(src));
                }
            }
            asm volatile("cp.async.commit_group;\n");

            // Accumulate the previous stage while this one is in flight.
            if (st > 0) {
                asm volatile("cp.async.wait_group 1;\n");
                const int pb = (sbuf ^ 1) * 4;
                #pragma unroll
                for (int q = 0; q < 4; ++q) {
                    if (q < prevcnt) {
                        float4 v = buf[warp][pb + q][lane];
                        if (q & 1) { a1.x += v.x; a1.y += v.y; a1.z += v.z; a1.w += v.w; }
                        else       { a0.x += v.x; a0.y += v.y; a0.z += v.z; a0.w += v.w; }
                    }
                }
            }
            prevcnt = cnt;
            sbuf ^= 1;
        }

        // Drain the last stage of this chunk.
        if (nstage > 0) {
            asm volatile("cp.async.wait_group 0;\n");
            const int pb = (sbuf ^ 1) * 4;
            #pragma unroll
            for (int q = 0; q < 4; ++q) {
                if (q < prevcnt) {
                    float4 v = buf[warp][pb + q][lane];
                    if (q & 1) { a1.x += v.x; a1.y += v.y; a1.z += v.z; a1.w += v.w; }
                    else       { a0.x += v.x; a0.y += v.y; a0.z += v.z; a0.w += v.w; }
                }
            }
        }
    }

    float4 acc;
    acc.x = a0.x + a1.x;
    acc.y = a0.y + a1.y;
    acc.z = a0.z + a1.z;
    acc.w = a0.w + a1.w;

    // out[b][f][:] — always write (empty bags must be 0; d_out is poisoned)
    float4* o = reinterpret_cast<float4*>(out) + ((size_t)bag * F + f) * 32;
    o[lane] = acc;
}

extern "C" void kernel_launch(void* const* d_in, const int* in_sizes, int n_in,
                              void* d_out, int out_size) {
    const float* tables  = (const float*)d_in[0];
    const int*   values  = (const int*)d_in[1];
    const int*   offsets = (const int*)d_in[2];
    float* out = (float*)d_out;

    dim3 grid(B / 2, F);   // feature on y: blocks of one feature grouped -> L2 reuse
    dim3 block(64);        // 2 warps = 2 bags per block
    ebag_pool_kernel<<<grid, block>>>(tables, values, offsets, out);
}